// round 5
// baseline (speedup 1.0000x reference)
#include <cuda_runtime.h>
#include <cuda_bf16.h>
#include <cstdint>

#define BATCH   512
#define SEQL    512
#define VOCAB   50000
#define EMBD    100
#define HD      100
#define G4      400
#define HIDM    50
#define KT      20
#define NEGF    (-1.0e6f)

// ------------- device scratch (no cudaMalloc allowed) -------------
__device__ float g_proj[2ull * VOCAB * G4];            // emb @ Wih^T per dir
__device__ float g_enc [(size_t)BATCH * SEQL * 200];   // [hf | hb]
__device__ float g_probs[(size_t)BATCH * SEQL * KT];

// ------------- packed f32x2 helpers -------------
__device__ __forceinline__ unsigned long long pack2(float lo, float hi) {
    unsigned long long r;
    asm("mov.b64 %0, {%1, %2};" : "=l"(r) : "f"(lo), "f"(hi));
    return r;
}
__device__ __forceinline__ void unpack2(unsigned long long v, float& lo, float& hi) {
    asm("mov.b64 {%0, %1}, %2;" : "=f"(lo), "=f"(hi) : "l"(v));
}
__device__ __forceinline__ unsigned long long fma2(unsigned long long a,
                                                   unsigned long long b,
                                                   unsigned long long c) {
    unsigned long long d;
    asm("fma.rn.f32x2 %0, %1, %2, %3;" : "=l"(d) : "l"(a), "l"(b), "l"(c));
    return d;
}
__device__ __forceinline__ unsigned long long add2(unsigned long long a,
                                                   unsigned long long b) {
    unsigned long long d;
    asm("add.rn.f32x2 %0, %1, %2;" : "=l"(d) : "l"(a), "l"(b));
    return d;
}
__device__ __forceinline__ float sigf(float x) {
    return __fdividef(1.0f, 1.0f + __expf(-x));
}
__device__ __forceinline__ float tanhf_(float x) {
    float xa = fminf(fmaxf(x, -15.0f), 15.0f);
    float e = __expf(-2.0f * xa);
    return __fdividef(1.0f - e, 1.0f + e);
}

// =====================================================================
// K1: proj[dir][v][g] = sum_k emb[v][k] * Wih_dir[g][k]
// grid (ceil(V/64), 2), 200 threads. 64 vocab rows, gates in 4 chunks of 100.
// =====================================================================
#define PROJ_SMEM ((6656 + 10400) * 4)
__global__ void proj_kernel(const float* __restrict__ emb,
                            const float* __restrict__ Wih_f,
                            const float* __restrict__ Wih_b) {
    extern __shared__ float sm[];
    float* embS = sm;         // [64][104]
    float* wT   = sm + 6656;  // [100][104]  wT[k][g']

    const int dir = blockIdx.y;
    const float* Wih = dir ? Wih_b : Wih_f;
    float* projD = g_proj + (size_t)dir * VOCAB * G4;

    const int tid = threadIdx.x;
    const int v0  = blockIdx.x * 64;
    const int gx  = tid % 25;   // gate quad (g' = gx*4)
    const int vy  = tid / 25;   // 0..7

    for (int i = tid; i < 64 * EMBD; i += 200) {
        int v = i / EMBD, k = i % EMBD;
        embS[v * 104 + k] = (v0 + v < VOCAB) ? emb[(size_t)(v0 + v) * EMBD + k] : 0.0f;
    }
    for (int ch = 0; ch < 4; ++ch) {
        __syncthreads();
        for (int i = tid; i < 100 * 100; i += 200) {
            int gp = i / 100, k = i % 100;
            wT[k * 104 + gp] = Wih[(size_t)(ch * 100 + gp) * EMBD + k];
        }
        __syncthreads();

        float acc[8][4];
        #pragma unroll
        for (int s = 0; s < 8; ++s)
            acc[s][0] = acc[s][1] = acc[s][2] = acc[s][3] = 0.0f;
        for (int k = 0; k < 100; ++k) {
            float4 wv = *(const float4*)&wT[k * 104 + gx * 4];
            #pragma unroll
            for (int s = 0; s < 8; ++s) {
                float e = embS[(vy * 8 + s) * 104 + k];
                acc[s][0] += e * wv.x;
                acc[s][1] += e * wv.y;
                acc[s][2] += e * wv.z;
                acc[s][3] += e * wv.w;
            }
        }
        #pragma unroll
        for (int s = 0; s < 8; ++s) {
            int v = v0 + vy * 8 + s;
            if (v < VOCAB) {
                float4 o = make_float4(acc[s][0], acc[s][1], acc[s][2], acc[s][3]);
                *(float4*)&projD[(size_t)v * G4 + ch * 100 + gx * 4] = o;
            }
        }
    }
}

// =====================================================================
// K2: persistent BiLSTM. grid (64, 2); block owns 8 batch rows; 416 threads.
// tid<400: thread per gate column (gemm) / per (rowpair,hidden) (cell).
// tid 400..407: next-step token prefetch.
// =====================================================================
#define LSTM_SMEM 176128
__global__ __launch_bounds__(416, 1)
void lstm_kernel(const int* __restrict__ X, const int* __restrict__ lengths,
                 const float* __restrict__ Whh_f, const float* __restrict__ b_f,
                 const float* __restrict__ Whh_b, const float* __restrict__ b_b,
                 const float* __restrict__ h0, const float* __restrict__ c0) {
    extern __shared__ char smraw[];
    float* whhT = (float*)smraw;                                     // [100][400]
    unsigned long long* hsh = (unsigned long long*)(smraw + 160000); // [100][4]
    unsigned long long* gsh = (unsigned long long*)(smraw + 163200); // [4][400]
    int* tokS = (int*)(smraw + 176000);                              // [2][8]
    int* lenS = tokS + 16;                                           // [8]

    const int dir = blockIdx.y;
    const int b0  = blockIdx.x * 8;
    const int tid = threadIdx.x;
    const float* Whh = dir ? Whh_b : Whh_f;
    const float* bia = dir ? b_b : b_f;
    const float* proj = g_proj + (size_t)dir * VOCAB * G4;

    for (int i = tid; i < G4 * HD; i += blockDim.x) {
        int g = i / HD, k = i % HD;
        whhT[k * G4 + g] = Whh[i];
    }
    if (tid < 8) lenS[tid] = lengths[b0 + tid];

    const int q = tid < 400 ? tid / 100 : 0;  // rowpair (rows 2q,2q+1)
    const int j = tid < 400 ? tid % 100 : 0;
    float c_lo = 0.f, c_hi = 0.f;
    if (tid < 400) {
        int r0 = b0 + 2 * q, r1 = r0 + 1;
        float hlo = h0[((size_t)dir * BATCH + r0) * HD + j];
        float hhi = h0[((size_t)dir * BATCH + r1) * HD + j];
        hsh[j * 4 + q] = pack2(hlo, hhi);
        c_lo = c0[((size_t)dir * BATCH + r0) * HD + j];
        c_hi = c0[((size_t)dir * BATCH + r1) * HD + j];
    }
    const float bg = (tid < 400) ? bia[tid] : 0.0f;
    __syncthreads();

    int lenmax = lenS[0];
    #pragma unroll
    for (int r = 1; r < 8; ++r) lenmax = max(lenmax, lenS[r]);

    if (tid < 8) {  // tokens for t = 0
        int len = lenS[tid];
        int it = dir ? (len - 1) : 0;
        tokS[tid] = X[(size_t)(b0 + tid) * SEQL + it];
    }
    __syncthreads();

    for (int t = 0; t < lenmax; ++t) {
        const int buf = t & 1;
        if (tid < 400) {
            const int g = tid;
            float xv[8];
            #pragma unroll
            for (int r = 0; r < 8; ++r)
                xv[r] = __ldg(proj + (size_t)tokS[buf * 8 + r] * G4 + g);

            unsigned long long a0 = 0, a1 = 0, a2 = 0, a3 = 0;
            const float* wp = whhT + g;
            const ulonglong2* hp = (const ulonglong2*)hsh;
            #pragma unroll 10
            for (int k = 0; k < 100; ++k) {
                float w = wp[k * G4];
                unsigned long long w2 = pack2(w, w);
                ulonglong2 hA = hp[2 * k];
                ulonglong2 hB = hp[2 * k + 1];
                a0 = fma2(hA.x, w2, a0);
                a1 = fma2(hA.y, w2, a1);
                a2 = fma2(hB.x, w2, a2);
                a3 = fma2(hB.y, w2, a3);
            }
            gsh[0 * G4 + g] = add2(a0, pack2(xv[0] + bg, xv[1] + bg));
            gsh[1 * G4 + g] = add2(a1, pack2(xv[2] + bg, xv[3] + bg));
            gsh[2 * G4 + g] = add2(a2, pack2(xv[4] + bg, xv[5] + bg));
            gsh[3 * G4 + g] = add2(a3, pack2(xv[6] + bg, xv[7] + bg));
        }
        __syncthreads();

        if (tid < 400) {
            float i_lo, i_hi, f_lo, f_hi, gg_lo, gg_hi, o_lo, o_hi;
            unpack2(gsh[q * G4 + j],       i_lo, i_hi);
            unpack2(gsh[q * G4 + 100 + j], f_lo, f_hi);
            unpack2(gsh[q * G4 + 200 + j], gg_lo, gg_hi);
            unpack2(gsh[q * G4 + 300 + j], o_lo, o_hi);

            c_lo = sigf(f_lo) * c_lo + sigf(i_lo) * tanhf_(gg_lo);
            c_hi = sigf(f_hi) * c_hi + sigf(i_hi) * tanhf_(gg_hi);
            float h_lo = sigf(o_lo) * tanhf_(c_lo);
            float h_hi = sigf(o_hi) * tanhf_(c_hi);
            hsh[j * 4 + q] = pack2(h_lo, h_hi);

            int r0 = 2 * q, r1 = r0 + 1;
            int len0 = lenS[r0], len1 = lenS[r1];
            int ot0 = dir ? ((t < len0) ? (len0 - 1 - t) : t) : t;
            int ot1 = dir ? ((t < len1) ? (len1 - 1 - t) : t) : t;
            g_enc[((size_t)(b0 + r0) * SEQL + ot0) * 200 + dir * HD + j] = h_lo;
            g_enc[((size_t)(b0 + r1) * SEQL + ot1) * 200 + dir * HD + j] = h_hi;
        } else if (tid < 408) {
            int r = tid - 400, len = lenS[r];
            int tn = t + 1; if (tn >= SEQL) tn = SEQL - 1;
            int it = dir ? ((tn < len) ? (len - 1 - tn) : tn) : tn;
            tokS[(buf ^ 1) * 8 + r] = X[(size_t)(b0 + r) * SEQL + it];
        }
        __syncthreads();
    }
}

// =====================================================================
// K3: probs = relu(enc @ W1^T + b1) @ W2^T + b2 ; 32 tokens/block, 200 thr
// =====================================================================
#define MLP_SMEM (19080 * 4)
__global__ void mlp_kernel(const float* __restrict__ W1, const float* __restrict__ b1,
                           const float* __restrict__ W2, const float* __restrict__ b2) {
    extern __shared__ float sm[];
    float* encS = sm;          // [32][200]
    float* w1T  = sm + 6400;   // [200][50]
    float* hidS = sm + 16400;  // [32][50]
    float* w2T  = sm + 18000;  // [50][20]
    float* b1S  = sm + 19000;  // [50]
    float* b2S  = sm + 19056;  // [20]

    const int tid = threadIdx.x;
    const size_t tok0 = (size_t)blockIdx.x * 32;

    for (int i = tid; i < 32 * 200; i += 200) encS[i] = g_enc[tok0 * 200 + i];
    for (int i = tid; i < HIDM * 200; i += 200) {
        int m = i / 200, k = i % 200;
        w1T[k * HIDM + m] = W1[i];
    }
    for (int i = tid; i < KT * HIDM; i += 200) {
        int jj = i / HIDM, k = i % HIDM;
        w2T[k * KT + jj] = W2[i];
    }
    if (tid < HIDM) b1S[tid] = b1[tid];
    if (tid < KT)   b2S[tid] = b2[tid];
    __syncthreads();

    const int tg = tid / 25, mg = tid % 25;   // 4 toks x 2 hidden per thread
    float a00 = 0, a01 = 0, a10 = 0, a11 = 0, a20 = 0, a21 = 0, a30 = 0, a31 = 0;
    for (int k = 0; k < 200; ++k) {
        float w0 = w1T[k * HIDM + 2 * mg];
        float w1v = w1T[k * HIDM + 2 * mg + 1];
        float e0 = encS[(tg * 4 + 0) * 200 + k];
        float e1 = encS[(tg * 4 + 1) * 200 + k];
        float e2 = encS[(tg * 4 + 2) * 200 + k];
        float e3 = encS[(tg * 4 + 3) * 200 + k];
        a00 += e0 * w0; a01 += e0 * w1v;
        a10 += e1 * w0; a11 += e1 * w1v;
        a20 += e2 * w0; a21 += e2 * w1v;
        a30 += e3 * w0; a31 += e3 * w1v;
    }
    float bb0 = b1S[2 * mg], bb1 = b1S[2 * mg + 1];
    hidS[(tg * 4 + 0) * HIDM + 2 * mg]     = fmaxf(a00 + bb0, 0.f);
    hidS[(tg * 4 + 0) * HIDM + 2 * mg + 1] = fmaxf(a01 + bb1, 0.f);
    hidS[(tg * 4 + 1) * HIDM + 2 * mg]     = fmaxf(a10 + bb0, 0.f);
    hidS[(tg * 4 + 1) * HIDM + 2 * mg + 1] = fmaxf(a11 + bb1, 0.f);
    hidS[(tg * 4 + 2) * HIDM + 2 * mg]     = fmaxf(a20 + bb0, 0.f);
    hidS[(tg * 4 + 2) * HIDM + 2 * mg + 1] = fmaxf(a21 + bb1, 0.f);
    hidS[(tg * 4 + 3) * HIDM + 2 * mg]     = fmaxf(a30 + bb0, 0.f);
    hidS[(tg * 4 + 3) * HIDM + 2 * mg + 1] = fmaxf(a31 + bb1, 0.f);
    __syncthreads();

    for (int idx = tid; idx < 32 * KT; idx += 200) {
        int tk = idx / KT, jj = idx % KT;
        float acc = b2S[jj];
        #pragma unroll 10
        for (int k = 0; k < HIDM; ++k) acc += hidS[tk * HIDM + k] * w2T[k * KT + jj];
        g_probs[(tok0 + tk) * KT + jj] = acc;
    }
}

// =====================================================================
// K4: Viterbi. warp per batch row; grid 128 x 128 threads.
// =====================================================================
__global__ void viterbi_kernel(const float* __restrict__ trans,
                               const int* __restrict__ lengths,
                               float* __restrict__ out, int out_size) {
    __shared__ float transS[512];
    __shared__ unsigned char bp[4][SEQL][KT];

    const int tid = threadIdx.x;
    const int w = tid / 32, lane = tid % 32;
    const int b = blockIdx.x * 4 + w;

    for (int i = tid; i < 512; i += blockDim.x)
        transS[i] = (i < KT * KT) ? trans[i] : 0.0f;
    __syncthreads();

    const int len = lengths[b];
    const int ln = (lane < KT) ? lane : 0;
    float alpha = (lane == (KT - 2)) ? 0.0f : NEGF;   // START = K-2
    const float* pb = g_probs + (size_t)b * SEQL * KT;

    for (int t = 0; t < len; ++t) {
        float p = pb[(size_t)t * KT + ln];
        float best = -3.4e38f; int bi = 0;
        #pragma unroll
        for (int i = 0; i < KT; ++i) {
            float ai = __shfl_sync(0xffffffffu, alpha, i);
            float cand = ai + transS[i * KT + ln];
            if (cand > best) { best = cand; bi = i; }
        }
        alpha = best + p;
        if (lane < KT) bp[w][t][lane] = (unsigned char)bi;
    }

    float fin = alpha + transS[ln * KT + (KT - 1)];   // + trans[:, END]
    float best = -3.4e38f; int bj = 0;
    #pragma unroll
    for (int i = 0; i < KT; ++i) {
        float v = __shfl_sync(0xffffffffu, fin, i);
        if (v > best) { best = v; bj = i; }
    }

    if (lane == 0) {
        out[b] = best;
        if (out_size >= BATCH + BATCH * SEQL) {
            float* pout = out + BATCH + (size_t)b * SEQL;
            int cur = bj;
            for (int t = SEQL - 1; t >= 0; --t) {
                if (t >= len) {
                    pout[t] = -1.0f;
                } else {
                    pout[t] = (float)cur;
                    cur = bp[w][t][cur];
                }
            }
        }
    }
}

// =====================================================================
extern "C" void kernel_launch(void* const* d_in, const int* in_sizes, int n_in,
                              void* d_out, int out_size) {
    const int*   X       = (const int*)d_in[0];
    const int*   lengths = (const int*)d_in[1];
    const float* emb     = (const float*)d_in[2];
    const float* Wih_f   = (const float*)d_in[3];
    const float* Whh_f   = (const float*)d_in[4];
    const float* b_f     = (const float*)d_in[5];
    const float* Wih_b   = (const float*)d_in[6];
    const float* Whh_b   = (const float*)d_in[7];
    const float* b_b     = (const float*)d_in[8];
    const float* h0      = (const float*)d_in[9];
    const float* c0      = (const float*)d_in[10];
    const float* W1      = (const float*)d_in[11];
    const float* b1      = (const float*)d_in[12];
    const float* W2      = (const float*)d_in[13];
    const float* b2      = (const float*)d_in[14];
    const float* trans   = (const float*)d_in[15];
    float* out = (float*)d_out;

    static bool attr_done = false;
    if (!attr_done) {
        cudaFuncSetAttribute(proj_kernel, cudaFuncAttributeMaxDynamicSharedMemorySize, PROJ_SMEM);
        cudaFuncSetAttribute(lstm_kernel, cudaFuncAttributeMaxDynamicSharedMemorySize, LSTM_SMEM);
        cudaFuncSetAttribute(mlp_kernel,  cudaFuncAttributeMaxDynamicSharedMemorySize, MLP_SMEM);
        attr_done = true;
    }

    proj_kernel<<<dim3((VOCAB + 63) / 64, 2), 200, PROJ_SMEM>>>(emb, Wih_f, Wih_b);
    lstm_kernel<<<dim3(BATCH / 8, 2), 416, LSTM_SMEM>>>(X, lengths, Whh_f, b_f,
                                                        Whh_b, b_b, h0, c0);
    mlp_kernel<<<(BATCH * SEQL) / 32, 200, MLP_SMEM>>>(W1, b1, W2, b2);
    viterbi_kernel<<<BATCH / 4, 128>>>(trans, lengths, out, out_size);
}

// round 10
// speedup vs baseline: 1.0539x; 1.0539x over previous
#include <cuda_runtime.h>
#include <cuda_bf16.h>
#include <cstdint>

#define BATCH   512
#define SEQL    512
#define VOCAB   50000
#define EMBD    100
#define HD      100
#define G4      400
#define HIDM    50
#define KT      20
#define NEGF    (-1.0e6f)

// ------------- device scratch (no cudaMalloc allowed) -------------
__device__ float g_proj[2ull * VOCAB * G4];            // emb @ Wih^T per dir
__device__ float g_enc [(size_t)BATCH * SEQL * 200];   // [hf | hb]
__device__ float g_probs[(size_t)BATCH * SEQL * KT];

// ------------- packed f32x2 helpers -------------
__device__ __forceinline__ unsigned long long pack2(float lo, float hi) {
    unsigned long long r;
    asm("mov.b64 %0, {%1, %2};" : "=l"(r) : "f"(lo), "f"(hi));
    return r;
}
__device__ __forceinline__ void unpack2(unsigned long long v, float& lo, float& hi) {
    asm("mov.b64 {%0, %1}, %2;" : "=f"(lo), "=f"(hi) : "l"(v));
}
__device__ __forceinline__ unsigned long long fma2(unsigned long long a,
                                                   unsigned long long b,
                                                   unsigned long long c) {
    unsigned long long d;
    asm("fma.rn.f32x2 %0, %1, %2, %3;" : "=l"(d) : "l"(a), "l"(b), "l"(c));
    return d;
}
__device__ __forceinline__ unsigned long long add2(unsigned long long a,
                                                   unsigned long long b) {
    unsigned long long d;
    asm("add.rn.f32x2 %0, %1, %2;" : "=l"(d) : "l"(a), "l"(b));
    return d;
}
__device__ __forceinline__ float sigf(float x) {
    return __fdividef(1.0f, 1.0f + __expf(-x));
}
__device__ __forceinline__ float tanhf_(float x) {
    float xa = fminf(fmaxf(x, -15.0f), 15.0f);
    float e = __expf(-2.0f * xa);
    return __fdividef(1.0f - e, 1.0f + e);
}
// first-max (lowest index on tie) combiner — pairing-safe
__device__ __forceinline__ void amax2(float& va, int& ia, float vb, int ib) {
    if (vb > va || (vb == va && ib < ia)) { va = vb; ia = ib; }
}

// =====================================================================
// K1: proj[dir][v][g] = sum_k emb[v][k] * Wih_dir[g][k]
// grid (ceil(V/64), 2), 200 threads. f32x2-packed over vocab-row pairs.
// =====================================================================
#define PROJ_SMEM ((6600 + 10400) * 4)
__global__ void proj_kernel(const float* __restrict__ emb,
                            const float* __restrict__ Wih_f,
                            const float* __restrict__ Wih_b) {
    extern __shared__ float sm[];
    float* embT = sm;         // [100][66]  embT[k][v]
    float* wT   = sm + 6600;  // [100][104] wT[k][g']

    const int dir = blockIdx.y;
    const float* Wih = dir ? Wih_b : Wih_f;
    float* projD = g_proj + (size_t)dir * VOCAB * G4;

    const int tid = threadIdx.x;
    const int v0  = blockIdx.x * 64;
    const int gx  = tid % 25;   // gate quad (g' = gx*4)
    const int vy  = tid / 25;   // vocab octet 0..7

    // embT[k][v] = emb[v0+v][k] (zero-pad OOB)
    for (int i = tid; i < 64 * EMBD; i += 200) {
        int v = i / EMBD, k = i % EMBD;
        embT[k * 66 + v] = (v0 + v < VOCAB) ? emb[(size_t)(v0 + v) * EMBD + k] : 0.0f;
    }

    for (int ch = 0; ch < 4; ++ch) {
        __syncthreads();
        for (int i = tid; i < 100 * 100; i += 200) {
            int gp = i / 100, k = i % 100;
            wT[k * 104 + gp] = Wih[(size_t)(ch * 100 + gp) * EMBD + k];
        }
        __syncthreads();

        unsigned long long acc[4][4];
        #pragma unroll
        for (int p = 0; p < 4; ++p)
            acc[p][0] = acc[p][1] = acc[p][2] = acc[p][3] = 0ull;

        for (int k = 0; k < 100; ++k) {
            float4 wv = *(const float4*)&wT[k * 104 + gx * 4];
            unsigned long long w0 = pack2(wv.x, wv.x);
            unsigned long long w1 = pack2(wv.y, wv.y);
            unsigned long long w2 = pack2(wv.z, wv.z);
            unsigned long long w3 = pack2(wv.w, wv.w);
            #pragma unroll
            for (int p = 0; p < 4; ++p) {
                unsigned long long e2 =
                    *(const unsigned long long*)&embT[k * 66 + vy * 8 + 2 * p];
                acc[p][0] = fma2(e2, w0, acc[p][0]);
                acc[p][1] = fma2(e2, w1, acc[p][1]);
                acc[p][2] = fma2(e2, w2, acc[p][2]);
                acc[p][3] = fma2(e2, w3, acc[p][3]);
            }
        }
        #pragma unroll
        for (int p = 0; p < 4; ++p) {
            float lo[4], hi[4];
            #pragma unroll
            for (int x = 0; x < 4; ++x) unpack2(acc[p][x], lo[x], hi[x]);
            int vA = v0 + vy * 8 + 2 * p, vB = vA + 1;
            if (vA < VOCAB) {
                float4 o = make_float4(lo[0], lo[1], lo[2], lo[3]);
                *(float4*)&projD[(size_t)vA * G4 + ch * 100 + gx * 4] = o;
            }
            if (vB < VOCAB) {
                float4 o = make_float4(hi[0], hi[1], hi[2], hi[3]);
                *(float4*)&projD[(size_t)vB * G4 + ch * 100 + gx * 4] = o;
            }
        }
    }
}

// =====================================================================
// K2: persistent BiLSTM. grid (64, 2); block owns 8 batch rows; 416 threads.
// (unchanged from R4 — passed; profile next round decides further work)
// =====================================================================
#define LSTM_SMEM 176128
__global__ __launch_bounds__(416, 1)
void lstm_kernel(const int* __restrict__ X, const int* __restrict__ lengths,
                 const float* __restrict__ Whh_f, const float* __restrict__ b_f,
                 const float* __restrict__ Whh_b, const float* __restrict__ b_b,
                 const float* __restrict__ h0, const float* __restrict__ c0) {
    extern __shared__ char smraw[];
    float* whhT = (float*)smraw;                                     // [100][400]
    unsigned long long* hsh = (unsigned long long*)(smraw + 160000); // [100][4]
    unsigned long long* gsh = (unsigned long long*)(smraw + 163200); // [4][400]
    int* tokS = (int*)(smraw + 176000);                              // [2][8]
    int* lenS = tokS + 16;                                           // [8]

    const int dir = blockIdx.y;
    const int b0  = blockIdx.x * 8;
    const int tid = threadIdx.x;
    const float* Whh = dir ? Whh_b : Whh_f;
    const float* bia = dir ? b_b : b_f;
    const float* proj = g_proj + (size_t)dir * VOCAB * G4;

    for (int i = tid; i < G4 * HD; i += blockDim.x) {
        int g = i / HD, k = i % HD;
        whhT[k * G4 + g] = Whh[i];
    }
    if (tid < 8) lenS[tid] = lengths[b0 + tid];

    const int q = tid < 400 ? tid / 100 : 0;
    const int j = tid < 400 ? tid % 100 : 0;
    float c_lo = 0.f, c_hi = 0.f;
    if (tid < 400) {
        int r0 = b0 + 2 * q, r1 = r0 + 1;
        float hlo = h0[((size_t)dir * BATCH + r0) * HD + j];
        float hhi = h0[((size_t)dir * BATCH + r1) * HD + j];
        hsh[j * 4 + q] = pack2(hlo, hhi);
        c_lo = c0[((size_t)dir * BATCH + r0) * HD + j];
        c_hi = c0[((size_t)dir * BATCH + r1) * HD + j];
    }
    const float bg = (tid < 400) ? bia[tid] : 0.0f;
    __syncthreads();

    int lenmax = lenS[0];
    #pragma unroll
    for (int r = 1; r < 8; ++r) lenmax = max(lenmax, lenS[r]);

    if (tid < 8) {
        int len = lenS[tid];
        int it = dir ? (len - 1) : 0;
        tokS[tid] = X[(size_t)(b0 + tid) * SEQL + it];
    }
    __syncthreads();

    for (int t = 0; t < lenmax; ++t) {
        const int buf = t & 1;
        if (tid < 400) {
            const int g = tid;
            float xv[8];
            #pragma unroll
            for (int r = 0; r < 8; ++r)
                xv[r] = __ldg(proj + (size_t)tokS[buf * 8 + r] * G4 + g);

            unsigned long long a0 = 0, a1 = 0, a2 = 0, a3 = 0;
            const float* wp = whhT + g;
            const ulonglong2* hp = (const ulonglong2*)hsh;
            #pragma unroll 10
            for (int k = 0; k < 100; ++k) {
                float w = wp[k * G4];
                unsigned long long w2 = pack2(w, w);
                ulonglong2 hA = hp[2 * k];
                ulonglong2 hB = hp[2 * k + 1];
                a0 = fma2(hA.x, w2, a0);
                a1 = fma2(hA.y, w2, a1);
                a2 = fma2(hB.x, w2, a2);
                a3 = fma2(hB.y, w2, a3);
            }
            gsh[0 * G4 + g] = add2(a0, pack2(xv[0] + bg, xv[1] + bg));
            gsh[1 * G4 + g] = add2(a1, pack2(xv[2] + bg, xv[3] + bg));
            gsh[2 * G4 + g] = add2(a2, pack2(xv[4] + bg, xv[5] + bg));
            gsh[3 * G4 + g] = add2(a3, pack2(xv[6] + bg, xv[7] + bg));
        }
        __syncthreads();

        if (tid < 400) {
            float i_lo, i_hi, f_lo, f_hi, gg_lo, gg_hi, o_lo, o_hi;
            unpack2(gsh[q * G4 + j],       i_lo, i_hi);
            unpack2(gsh[q * G4 + 100 + j], f_lo, f_hi);
            unpack2(gsh[q * G4 + 200 + j], gg_lo, gg_hi);
            unpack2(gsh[q * G4 + 300 + j], o_lo, o_hi);

            c_lo = sigf(f_lo) * c_lo + sigf(i_lo) * tanhf_(gg_lo);
            c_hi = sigf(f_hi) * c_hi + sigf(i_hi) * tanhf_(gg_hi);
            float h_lo = sigf(o_lo) * tanhf_(c_lo);
            float h_hi = sigf(o_hi) * tanhf_(c_hi);
            hsh[j * 4 + q] = pack2(h_lo, h_hi);

            int r0 = 2 * q, r1 = r0 + 1;
            int len0 = lenS[r0], len1 = lenS[r1];
            int ot0 = dir ? ((t < len0) ? (len0 - 1 - t) : t) : t;
            int ot1 = dir ? ((t < len1) ? (len1 - 1 - t) : t) : t;
            g_enc[((size_t)(b0 + r0) * SEQL + ot0) * 200 + dir * HD + j] = h_lo;
            g_enc[((size_t)(b0 + r1) * SEQL + ot1) * 200 + dir * HD + j] = h_hi;
        } else if (tid < 408) {
            int r = tid - 400, len = lenS[r];
            int tn = t + 1; if (tn >= SEQL) tn = SEQL - 1;
            int it = dir ? ((tn < len) ? (len - 1 - tn) : tn) : tn;
            tokS[(buf ^ 1) * 8 + r] = X[(size_t)(b0 + r) * SEQL + it];
        }
        __syncthreads();
    }
}

// =====================================================================
// K3: MLP, 64 tokens/block, 200 threads, f32x2-packed over token pairs.
// encT/hidT stored transposed [feature][token] for LDS.64 pairs.
// =====================================================================
#define MLP_SMEM (27984 * 4)
__global__ void mlp_kernel(const float* __restrict__ W1, const float* __restrict__ b1,
                           const float* __restrict__ W2, const float* __restrict__ b2) {
    extern __shared__ float sm[];
    float* encT = sm;            // [200][66]  encT[k][tok]
    float* w1T  = sm + 13200;    // [200][52]  w1T[k][m]
    float* hidT = sm + 23600;    // [50][66]   hidT[m][tok]
    float* w2T  = sm + 26900;    // [50][20]   w2T[m][j]
    float* b1S  = sm + 27900;    // [50]
    float* b2S  = sm + 27952;    // [20]

    const int tid = threadIdx.x;
    const size_t tok0 = (size_t)blockIdx.x * 64;

    for (int i = tid; i < 64 * 200; i += 200) {
        int t = i / 200, k = i % 200;
        encT[k * 66 + t] = g_enc[(tok0 + t) * 200 + k];
    }
    for (int i = tid; i < HIDM * 200; i += 200) {
        int m = i / 200, k = i % 200;
        w1T[k * 52 + m] = W1[i];
    }
    for (int i = tid; i < KT * HIDM; i += 200) {
        int jj = i / HIDM, m = i % HIDM;
        w2T[m * KT + jj] = W2[i];
    }
    if (tid < HIDM) b1S[tid] = b1[tid];
    if (tid < KT)   b2S[tid] = b2[tid];
    __syncthreads();

    // stage 1: mg = hidden pair (2mg, 2mg+1), tg = token octet
    const int mg = tid % 25, tg = tid / 25;
    {
        unsigned long long acc0[4] = {0, 0, 0, 0};
        unsigned long long acc1[4] = {0, 0, 0, 0};
        for (int k = 0; k < 200; ++k) {
            float2 wp = *(const float2*)&w1T[k * 52 + 2 * mg];
            unsigned long long wA = pack2(wp.x, wp.x);
            unsigned long long wB = pack2(wp.y, wp.y);
            #pragma unroll
            for (int p = 0; p < 4; ++p) {
                unsigned long long e2 =
                    *(const unsigned long long*)&encT[k * 66 + tg * 8 + 2 * p];
                acc0[p] = fma2(e2, wA, acc0[p]);
                acc1[p] = fma2(e2, wB, acc1[p]);
            }
        }
        float bb0 = b1S[2 * mg], bb1 = b1S[2 * mg + 1];
        #pragma unroll
        for (int p = 0; p < 4; ++p) {
            float x0, x1, y0, y1;
            unpack2(acc0[p], x0, x1);
            unpack2(acc1[p], y0, y1);
            int tk = tg * 8 + 2 * p;
            hidT[(2 * mg) * 66 + tk]     = fmaxf(x0 + bb0, 0.f);
            hidT[(2 * mg) * 66 + tk + 1] = fmaxf(x1 + bb0, 0.f);
            hidT[(2 * mg + 1) * 66 + tk]     = fmaxf(y0 + bb1, 0.f);
            hidT[(2 * mg + 1) * 66 + tk + 1] = fmaxf(y1 + bb1, 0.f);
        }
    }
    __syncthreads();

    // stage 2: 32 token pairs x 20 states = 640 items
    for (int it = tid; it < 32 * KT; it += 200) {
        int tp = it / KT, jj = it % KT;
        float bb = b2S[jj];
        unsigned long long acc = pack2(bb, bb);
        #pragma unroll 10
        for (int m = 0; m < HIDM; ++m) {
            unsigned long long h2 =
                *(const unsigned long long*)&hidT[m * 66 + 2 * tp];
            float w = w2T[m * KT + jj];
            acc = fma2(h2, pack2(w, w), acc);
        }
        float o0, o1;
        unpack2(acc, o0, o1);
        g_probs[(tok0 + 2 * tp) * KT + jj]     = o0;
        g_probs[(tok0 + 2 * tp + 1) * KT + jj] = o1;
    }
}

// =====================================================================
// K4: Viterbi. warp per batch row; tree argmax + prob prefetch.
// =====================================================================
__global__ void viterbi_kernel(const float* __restrict__ trans,
                               const int* __restrict__ lengths,
                               float* __restrict__ out, int out_size) {
    __shared__ float transS[416];
    __shared__ unsigned char bp[4][SEQL][KT];

    const int tid = threadIdx.x;
    const int w = tid / 32, lane = tid % 32;
    const int b = blockIdx.x * 4 + w;

    for (int i = tid; i < 416; i += blockDim.x)
        transS[i] = (i < KT * KT) ? trans[i] : 0.0f;
    __syncthreads();

    const int len = lengths[b];
    const int ln = (lane < KT) ? lane : 0;
    float alpha = (lane == (KT - 2)) ? 0.0f : NEGF;   // START = K-2
    const float* pb = g_probs + (size_t)b * SEQL * KT;

    float p_cur = pb[ln];
    for (int t = 0; t < len; ++t) {
        int tn = (t + 1 < len) ? (t + 1) : t;
        float p_nxt = pb[(size_t)tn * KT + ln];       // prefetch next step

        float v[KT]; int ix[KT];
        #pragma unroll
        for (int i = 0; i < KT; ++i) {
            float ai = __shfl_sync(0xffffffffu, alpha, i);
            v[i] = ai + transS[i * KT + ln];
            ix[i] = i;
        }
        #pragma unroll
        for (int i = 0; i < 4; ++i) amax2(v[i], ix[i], v[i + 16], ix[i + 16]);
        #pragma unroll
        for (int i = 0; i < 8; ++i) amax2(v[i], ix[i], v[i + 8], ix[i + 8]);
        #pragma unroll
        for (int i = 0; i < 4; ++i) amax2(v[i], ix[i], v[i + 4], ix[i + 4]);
        amax2(v[0], ix[0], v[2], ix[2]);
        amax2(v[1], ix[1], v[3], ix[3]);
        amax2(v[0], ix[0], v[1], ix[1]);

        alpha = v[0] + p_cur;
        if (lane < KT) bp[w][t][lane] = (unsigned char)ix[0];
        p_cur = p_nxt;
    }

    float fin = alpha + transS[ln * KT + (KT - 1)];   // + trans[:, END]
    float v[KT]; int ix[KT];
    #pragma unroll
    for (int i = 0; i < KT; ++i) {
        v[i] = __shfl_sync(0xffffffffu, fin, i);
        ix[i] = i;
    }
    #pragma unroll
    for (int i = 0; i < 4; ++i) amax2(v[i], ix[i], v[i + 16], ix[i + 16]);
    #pragma unroll
    for (int i = 0; i < 8; ++i) amax2(v[i], ix[i], v[i + 8], ix[i + 8]);
    #pragma unroll
    for (int i = 0; i < 4; ++i) amax2(v[i], ix[i], v[i + 4], ix[i + 4]);
    amax2(v[0], ix[0], v[2], ix[2]);
    amax2(v[1], ix[1], v[3], ix[3]);
    amax2(v[0], ix[0], v[1], ix[1]);

    if (lane == 0) {
        out[b] = v[0];
        if (out_size >= BATCH + BATCH * SEQL) {
            float* pout = out + BATCH + (size_t)b * SEQL;
            int cur = ix[0];
            for (int t = SEQL - 1; t >= 0; --t) {
                if (t >= len) {
                    pout[t] = -1.0f;
                } else {
                    pout[t] = (float)cur;
                    cur = bp[w][t][cur];
                }
            }
        }
    }
}

// =====================================================================
extern "C" void kernel_launch(void* const* d_in, const int* in_sizes, int n_in,
                              void* d_out, int out_size) {
    const int*   X       = (const int*)d_in[0];
    const int*   lengths = (const int*)d_in[1];
    const float* emb     = (const float*)d_in[2];
    const float* Wih_f   = (const float*)d_in[3];
    const float* Whh_f   = (const float*)d_in[4];
    const float* b_f     = (const float*)d_in[5];
    const float* Wih_b   = (const float*)d_in[6];
    const float* Whh_b   = (const float*)d_in[7];
    const float* b_b     = (const float*)d_in[8];
    const float* h0      = (const float*)d_in[9];
    const float* c0      = (const float*)d_in[10];
    const float* W1      = (const float*)d_in[11];
    const float* b1      = (const float*)d_in[12];
    const float* W2      = (const float*)d_in[13];
    const float* b2      = (const float*)d_in[14];
    const float* trans   = (const float*)d_in[15];
    float* out = (float*)d_out;

    static bool attr_done = false;
    if (!attr_done) {
        cudaFuncSetAttribute(proj_kernel, cudaFuncAttributeMaxDynamicSharedMemorySize, PROJ_SMEM);
        cudaFuncSetAttribute(lstm_kernel, cudaFuncAttributeMaxDynamicSharedMemorySize, LSTM_SMEM);
        cudaFuncSetAttribute(mlp_kernel,  cudaFuncAttributeMaxDynamicSharedMemorySize, MLP_SMEM);
        attr_done = true;
    }

    proj_kernel<<<dim3((VOCAB + 63) / 64, 2), 200, PROJ_SMEM>>>(emb, Wih_f, Wih_b);
    lstm_kernel<<<dim3(BATCH / 8, 2), 416, LSTM_SMEM>>>(X, lengths, Whh_f, b_f,
                                                        Whh_b, b_b, h0, c0);
    mlp_kernel<<<(BATCH * SEQL) / 64, 200, MLP_SMEM>>>(W1, b1, W2, b2);
    viterbi_kernel<<<BATCH / 4, 128>>>(trans, lengths, out, out_size);
}

// round 11
// speedup vs baseline: 1.1420x; 1.0835x over previous
#include <cuda_runtime.h>
#include <cuda_bf16.h>
#include <cstdint>

#define BATCH   512
#define SEQL    512
#define VOCAB   50000
#define EMBD    100
#define HD      100
#define G4      400
#define HIDM    50
#define KT      20
#define NEGF    (-1.0e6f)

typedef unsigned long long ull;

// ------------- device scratch (no cudaMalloc allowed) -------------
__device__ float g_proj[2ull * VOCAB * G4];            // emb @ Wih^T per dir
__device__ float g_enc [(size_t)BATCH * SEQL * 200];   // [hf | hb]
__device__ float g_probs[(size_t)BATCH * SEQL * KT];

// ------------- packed f32x2 helpers -------------
__device__ __forceinline__ ull pack2(float lo, float hi) {
    ull r;
    asm("mov.b64 %0, {%1, %2};" : "=l"(r) : "f"(lo), "f"(hi));
    return r;
}
__device__ __forceinline__ void unpack2(ull v, float& lo, float& hi) {
    asm("mov.b64 {%0, %1}, %2;" : "=f"(lo), "=f"(hi) : "l"(v));
}
__device__ __forceinline__ ull fma2(ull a, ull b, ull c) {
    ull d;
    asm("fma.rn.f32x2 %0, %1, %2, %3;" : "=l"(d) : "l"(a), "l"(b), "l"(c));
    return d;
}
__device__ __forceinline__ ull add2(ull a, ull b) {
    ull d;
    asm("add.rn.f32x2 %0, %1, %2;" : "=l"(d) : "l"(a), "l"(b));
    return d;
}
__device__ __forceinline__ float rcpf(float x) {
    float r;
    asm("rcp.approx.f32 %0, %1;" : "=f"(r) : "f"(x));
    return r;
}
// sigmoid: 1/(1+e^{-x})  (4 ops, 2 MUFU)
__device__ __forceinline__ float sigf(float x) {
    return rcpf(1.0f + __expf(-x));
}
// tanh: 1 - 2/(e^{2x}+1)  (5 ops, 2 MUFU, clamp-free: inf/0 limits give ±1)
__device__ __forceinline__ float tanhf_(float x) {
    return fmaf(-2.0f, rcpf(__expf(2.0f * x) + 1.0f), 1.0f);
}

// =====================================================================
// K1: proj[dir][v][g] = sum_k emb[v][k] * Wih_dir[g][k]
// grid (ceil(V/64), 2), 200 threads. f32x2-packed over vocab-row pairs.
// =====================================================================
#define PROJ_SMEM ((6600 + 10400) * 4)
__global__ void proj_kernel(const float* __restrict__ emb,
                            const float* __restrict__ Wih_f,
                            const float* __restrict__ Wih_b) {
    extern __shared__ float sm[];
    float* embT = sm;         // [100][66]  embT[k][v]
    float* wT   = sm + 6600;  // [100][104] wT[k][g']

    const int dir = blockIdx.y;
    const float* Wih = dir ? Wih_b : Wih_f;
    float* projD = g_proj + (size_t)dir * VOCAB * G4;

    const int tid = threadIdx.x;
    const int v0  = blockIdx.x * 64;
    const int gx  = tid % 25;
    const int vy  = tid / 25;

    for (int i = tid; i < 64 * EMBD; i += 200) {
        int v = i / EMBD, k = i % EMBD;
        embT[k * 66 + v] = (v0 + v < VOCAB) ? emb[(size_t)(v0 + v) * EMBD + k] : 0.0f;
    }

    for (int ch = 0; ch < 4; ++ch) {
        __syncthreads();
        for (int i = tid; i < 100 * 100; i += 200) {
            int gp = i / 100, k = i % 100;
            wT[k * 104 + gp] = Wih[(size_t)(ch * 100 + gp) * EMBD + k];
        }
        __syncthreads();

        ull acc[4][4];
        #pragma unroll
        for (int p = 0; p < 4; ++p)
            acc[p][0] = acc[p][1] = acc[p][2] = acc[p][3] = 0ull;

        for (int k = 0; k < 100; ++k) {
            float4 wv = *(const float4*)&wT[k * 104 + gx * 4];
            ull w0 = pack2(wv.x, wv.x);
            ull w1 = pack2(wv.y, wv.y);
            ull w2 = pack2(wv.z, wv.z);
            ull w3 = pack2(wv.w, wv.w);
            #pragma unroll
            for (int p = 0; p < 4; ++p) {
                ull e2 = *(const ull*)&embT[k * 66 + vy * 8 + 2 * p];
                acc[p][0] = fma2(e2, w0, acc[p][0]);
                acc[p][1] = fma2(e2, w1, acc[p][1]);
                acc[p][2] = fma2(e2, w2, acc[p][2]);
                acc[p][3] = fma2(e2, w3, acc[p][3]);
            }
        }
        #pragma unroll
        for (int p = 0; p < 4; ++p) {
            float lo[4], hi[4];
            #pragma unroll
            for (int x = 0; x < 4; ++x) unpack2(acc[p][x], lo[x], hi[x]);
            int vA = v0 + vy * 8 + 2 * p, vB = vA + 1;
            if (vA < VOCAB) {
                float4 o = make_float4(lo[0], lo[1], lo[2], lo[3]);
                *(float4*)&projD[(size_t)vA * G4 + ch * 100 + gx * 4] = o;
            }
            if (vB < VOCAB) {
                float4 o = make_float4(hi[0], hi[1], hi[2], hi[3]);
                *(float4*)&projD[(size_t)vB * G4 + ch * 100 + gx * 4] = o;
            }
        }
    }
}

// =====================================================================
// K2: persistent BiLSTM. grid (64, 2); block owns 8 batch rows; 832 threads.
// K-split: group A (tid<400) does k in [0,50), group B (400..799) k in
// [50,100); partials summed in the cell phase. 26 warps -> 6.5/SMSP for
// latency cover. tid 800..807: next-step token prefetch.
// =====================================================================
#define LSTM_SMEM 188928
__global__ __launch_bounds__(832, 1)
void lstm_kernel(const int* __restrict__ X, const int* __restrict__ lengths,
                 const float* __restrict__ Whh_f, const float* __restrict__ b_f,
                 const float* __restrict__ Whh_b, const float* __restrict__ b_b,
                 const float* __restrict__ h0, const float* __restrict__ c0) {
    extern __shared__ char smraw[];
    float* whhT = (float*)smraw;                 // [100][400]        160000 B
    ull*   hsh  = (ull*)(smraw + 160000);        // [100][4]          3200 B
    ull*   gshA = (ull*)(smraw + 163200);        // [4][400]          12800 B
    ull*   gshB = (ull*)(smraw + 176000);        // [4][400]          12800 B
    int*   tokS = (int*)(smraw + 188800);        // [2][8]
    int*   lenS = tokS + 16;                     // [8]

    const int dir = blockIdx.y;
    const int b0  = blockIdx.x * 8;
    const int tid = threadIdx.x;
    const float* Whh = dir ? Whh_b : Whh_f;
    const float* bia = dir ? b_b : b_f;
    const float* proj = g_proj + (size_t)dir * VOCAB * G4;

    for (int i = tid; i < G4 * HD; i += blockDim.x) {
        int g = i / HD, k = i % HD;
        whhT[k * G4 + g] = Whh[i];
    }
    if (tid < 8) lenS[tid] = lengths[b0 + tid];

    const int q = tid < 400 ? tid / 100 : 0;   // rowpair (rows 2q, 2q+1)
    const int j = tid < 400 ? tid % 100 : 0;
    float c_lo = 0.f, c_hi = 0.f;
    if (tid < 400) {
        int r0 = b0 + 2 * q, r1 = r0 + 1;
        float hlo = h0[((size_t)dir * BATCH + r0) * HD + j];
        float hhi = h0[((size_t)dir * BATCH + r1) * HD + j];
        hsh[j * 4 + q] = pack2(hlo, hhi);
        c_lo = c0[((size_t)dir * BATCH + r0) * HD + j];
        c_hi = c0[((size_t)dir * BATCH + r1) * HD + j];
    }
    const float bg = (tid < 400) ? bia[tid] : 0.0f;
    __syncthreads();

    int lenmax = lenS[0];
    #pragma unroll
    for (int r = 1; r < 8; ++r) lenmax = max(lenmax, lenS[r]);

    if (tid < 8) {
        int len = lenS[tid];
        int it = dir ? (len - 1) : 0;
        tokS[tid] = X[(size_t)(b0 + tid) * SEQL + it];
    }
    __syncthreads();

    for (int t = 0; t < lenmax; ++t) {
        const int buf = t & 1;
        // ---------- phase 1: split gemm ----------
        if (tid < 800) {
            const int g  = (tid < 400) ? tid : (tid - 400);
            const int kb = (tid < 400) ? 0 : 50;

            float xv[8];
            if (tid < 400) {
                #pragma unroll
                for (int r = 0; r < 8; ++r)
                    xv[r] = __ldg(proj + (size_t)tokS[buf * 8 + r] * G4 + g);
            }

            ull a0 = 0, a1 = 0, a2 = 0, a3 = 0;
            const float* wp = whhT + g;
            const ulonglong2* hp = (const ulonglong2*)hsh;
            #pragma unroll 10
            for (int k = kb; k < kb + 50; ++k) {
                float w = wp[k * G4];
                ull w2 = pack2(w, w);
                ulonglong2 hA = hp[2 * k];
                ulonglong2 hB = hp[2 * k + 1];
                a0 = fma2(hA.x, w2, a0);
                a1 = fma2(hA.y, w2, a1);
                a2 = fma2(hB.x, w2, a2);
                a3 = fma2(hB.y, w2, a3);
            }
            if (tid < 400) {
                a0 = add2(a0, pack2(xv[0] + bg, xv[1] + bg));
                a1 = add2(a1, pack2(xv[2] + bg, xv[3] + bg));
                a2 = add2(a2, pack2(xv[4] + bg, xv[5] + bg));
                a3 = add2(a3, pack2(xv[6] + bg, xv[7] + bg));
                gshA[0 * G4 + g] = a0;
                gshA[1 * G4 + g] = a1;
                gshA[2 * G4 + g] = a2;
                gshA[3 * G4 + g] = a3;
            } else {
                gshB[0 * G4 + g] = a0;
                gshB[1 * G4 + g] = a1;
                gshB[2 * G4 + g] = a2;
                gshB[3 * G4 + g] = a3;
            }
        }
        __syncthreads();

        // ---------- phase 2: cell + token prefetch ----------
        if (tid < 400) {
            ull iP = add2(gshA[q * G4 + j],       gshB[q * G4 + j]);
            ull fP = add2(gshA[q * G4 + 100 + j], gshB[q * G4 + 100 + j]);
            ull gP = add2(gshA[q * G4 + 200 + j], gshB[q * G4 + 200 + j]);
            ull oP = add2(gshA[q * G4 + 300 + j], gshB[q * G4 + 300 + j]);

            float i_lo, i_hi, f_lo, f_hi, gg_lo, gg_hi, o_lo, o_hi;
            unpack2(iP, i_lo, i_hi);
            unpack2(fP, f_lo, f_hi);
            unpack2(gP, gg_lo, gg_hi);
            unpack2(oP, o_lo, o_hi);

            c_lo = sigf(f_lo) * c_lo + sigf(i_lo) * tanhf_(gg_lo);
            c_hi = sigf(f_hi) * c_hi + sigf(i_hi) * tanhf_(gg_hi);
            float h_lo = sigf(o_lo) * tanhf_(c_lo);
            float h_hi = sigf(o_hi) * tanhf_(c_hi);
            hsh[j * 4 + q] = pack2(h_lo, h_hi);

            int r0 = 2 * q, r1 = r0 + 1;
            int len0 = lenS[r0], len1 = lenS[r1];
            int ot0 = dir ? ((t < len0) ? (len0 - 1 - t) : t) : t;
            int ot1 = dir ? ((t < len1) ? (len1 - 1 - t) : t) : t;
            g_enc[((size_t)(b0 + r0) * SEQL + ot0) * 200 + dir * HD + j] = h_lo;
            g_enc[((size_t)(b0 + r1) * SEQL + ot1) * 200 + dir * HD + j] = h_hi;
        } else if (tid >= 800 && tid < 808) {
            int r = tid - 800, len = lenS[r];
            int tn = t + 1; if (tn >= SEQL) tn = SEQL - 1;
            int it = dir ? ((tn < len) ? (len - 1 - tn) : tn) : tn;
            tokS[(buf ^ 1) * 8 + r] = X[(size_t)(b0 + r) * SEQL + it];
        }
        __syncthreads();
    }
}

// =====================================================================
// K3: MLP, 64 tokens/block, 200 threads, f32x2-packed over token pairs.
// =====================================================================
#define MLP_SMEM (27984 * 4)
__global__ void mlp_kernel(const float* __restrict__ W1, const float* __restrict__ b1,
                           const float* __restrict__ W2, const float* __restrict__ b2) {
    extern __shared__ float sm[];
    float* encT = sm;            // [200][66]
    float* w1T  = sm + 13200;    // [200][52]
    float* hidT = sm + 23600;    // [50][66]
    float* w2T  = sm + 26900;    // [50][20]
    float* b1S  = sm + 27900;    // [50]
    float* b2S  = sm + 27952;    // [20]

    const int tid = threadIdx.x;
    const size_t tok0 = (size_t)blockIdx.x * 64;

    for (int i = tid; i < 64 * 200; i += 200) {
        int t = i / 200, k = i % 200;
        encT[k * 66 + t] = g_enc[(tok0 + t) * 200 + k];
    }
    for (int i = tid; i < HIDM * 200; i += 200) {
        int m = i / 200, k = i % 200;
        w1T[k * 52 + m] = W1[i];
    }
    for (int i = tid; i < KT * HIDM; i += 200) {
        int jj = i / HIDM, m = i % HIDM;
        w2T[m * KT + jj] = W2[i];
    }
    if (tid < HIDM) b1S[tid] = b1[tid];
    if (tid < KT)   b2S[tid] = b2[tid];
    __syncthreads();

    const int mg = tid % 25, tg = tid / 25;
    {
        ull acc0[4] = {0, 0, 0, 0};
        ull acc1[4] = {0, 0, 0, 0};
        for (int k = 0; k < 200; ++k) {
            float2 wp = *(const float2*)&w1T[k * 52 + 2 * mg];
            ull wA = pack2(wp.x, wp.x);
            ull wB = pack2(wp.y, wp.y);
            #pragma unroll
            for (int p = 0; p < 4; ++p) {
                ull e2 = *(const ull*)&encT[k * 66 + tg * 8 + 2 * p];
                acc0[p] = fma2(e2, wA, acc0[p]);
                acc1[p] = fma2(e2, wB, acc1[p]);
            }
        }
        float bb0 = b1S[2 * mg], bb1 = b1S[2 * mg + 1];
        #pragma unroll
        for (int p = 0; p < 4; ++p) {
            float x0, x1, y0, y1;
            unpack2(acc0[p], x0, x1);
            unpack2(acc1[p], y0, y1);
            int tk = tg * 8 + 2 * p;
            hidT[(2 * mg) * 66 + tk]         = fmaxf(x0 + bb0, 0.f);
            hidT[(2 * mg) * 66 + tk + 1]     = fmaxf(x1 + bb0, 0.f);
            hidT[(2 * mg + 1) * 66 + tk]     = fmaxf(y0 + bb1, 0.f);
            hidT[(2 * mg + 1) * 66 + tk + 1] = fmaxf(y1 + bb1, 0.f);
        }
    }
    __syncthreads();

    for (int it = tid; it < 32 * KT; it += 200) {
        int tp = it / KT, jj = it % KT;
        float bb = b2S[jj];
        ull acc = pack2(bb, bb);
        #pragma unroll 10
        for (int m = 0; m < HIDM; ++m) {
            ull h2 = *(const ull*)&hidT[m * 66 + 2 * tp];
            float w = w2T[m * KT + jj];
            acc = fma2(h2, pack2(w, w), acc);
        }
        float o0, o1;
        unpack2(acc, o0, o1);
        g_probs[(tok0 + 2 * tp) * KT + jj]     = o0;
        g_probs[(tok0 + 2 * tp + 1) * KT + jj] = o1;
    }
}

// =====================================================================
// K4: Viterbi. warp per batch row; trans column in registers; argmax via
// fmax-tree + equality mask + ffs (exact first-max tie-break).
// =====================================================================
__global__ void viterbi_kernel(const float* __restrict__ trans,
                               const int* __restrict__ lengths,
                               float* __restrict__ out, int out_size) {
    __shared__ unsigned char bp[4][SEQL][KT];

    const int tid = threadIdx.x;
    const int w = tid / 32, lane = tid % 32;
    const int b = blockIdx.x * 4 + w;

    const int len = lengths[b];
    const int ln = (lane < KT) ? lane : 0;

    float trn[KT];
    #pragma unroll
    for (int i = 0; i < KT; ++i) trn[i] = trans[i * KT + ln];
    const float tend = trans[ln * KT + (KT - 1)];   // trans[:, END]

    float alpha = (lane == (KT - 2)) ? 0.0f : NEGF; // START = K-2
    const float* pb = g_probs + (size_t)b * SEQL * KT;

    float p_cur = pb[ln];
    for (int t = 0; t < len; ++t) {
        int tn = (t + 1 < len) ? (t + 1) : t;
        float p_nxt = pb[(size_t)tn * KT + ln];

        float v[KT];
        #pragma unroll
        for (int i = 0; i < KT; ++i) {
            float ai = __shfl_sync(0xffffffffu, alpha, i);
            v[i] = ai + trn[i];
        }
        float m[10];
        #pragma unroll
        for (int i = 0; i < 10; ++i) m[i] = fmaxf(v[i], v[i + 10]);
        #pragma unroll
        for (int i = 0; i < 5; ++i) m[i] = fmaxf(m[i], m[i + 5]);
        float best = fmaxf(fmaxf(fmaxf(m[0], m[1]), fmaxf(m[2], m[3])), m[4]);

        unsigned msk = 0;
        #pragma unroll
        for (int i = 0; i < KT; ++i)
            if (v[i] == best) msk |= (1u << i);
        int bi = __ffs(msk) - 1;

        alpha = best + p_cur;
        if (lane < KT) bp[w][t][lane] = (unsigned char)bi;
        p_cur = p_nxt;
    }

    float fin = alpha + tend;
    float v[KT];
    #pragma unroll
    for (int i = 0; i < KT; ++i) v[i] = __shfl_sync(0xffffffffu, fin, i);
    float m[10];
    #pragma unroll
    for (int i = 0; i < 10; ++i) m[i] = fmaxf(v[i], v[i + 10]);
    #pragma unroll
    for (int i = 0; i < 5; ++i) m[i] = fmaxf(m[i], m[i + 5]);
    float best = fmaxf(fmaxf(fmaxf(m[0], m[1]), fmaxf(m[2], m[3])), m[4]);
    unsigned msk = 0;
    #pragma unroll
    for (int i = 0; i < KT; ++i)
        if (v[i] == best) msk |= (1u << i);
    int bj = __ffs(msk) - 1;

    if (lane == 0) {
        out[b] = best;
        if (out_size >= BATCH + BATCH * SEQL) {
            float* pout = out + BATCH + (size_t)b * SEQL;
            int cur = bj;
            for (int t = SEQL - 1; t >= 0; --t) {
                if (t >= len) {
                    pout[t] = -1.0f;
                } else {
                    pout[t] = (float)cur;
                    cur = bp[w][t][cur];
                }
            }
        }
    }
}

// =====================================================================
extern "C" void kernel_launch(void* const* d_in, const int* in_sizes, int n_in,
                              void* d_out, int out_size) {
    const int*   X       = (const int*)d_in[0];
    const int*   lengths = (const int*)d_in[1];
    const float* emb     = (const float*)d_in[2];
    const float* Wih_f   = (const float*)d_in[3];
    const float* Whh_f   = (const float*)d_in[4];
    const float* b_f     = (const float*)d_in[5];
    const float* Wih_b   = (const float*)d_in[6];
    const float* Whh_b   = (const float*)d_in[7];
    const float* b_b     = (const float*)d_in[8];
    const float* h0      = (const float*)d_in[9];
    const float* c0      = (const float*)d_in[10];
    const float* W1      = (const float*)d_in[11];
    const float* b1      = (const float*)d_in[12];
    const float* W2      = (const float*)d_in[13];
    const float* b2      = (const float*)d_in[14];
    const float* trans   = (const float*)d_in[15];
    float* out = (float*)d_out;

    static bool attr_done = false;
    if (!attr_done) {
        cudaFuncSetAttribute(proj_kernel, cudaFuncAttributeMaxDynamicSharedMemorySize, PROJ_SMEM);
        cudaFuncSetAttribute(lstm_kernel, cudaFuncAttributeMaxDynamicSharedMemorySize, LSTM_SMEM);
        cudaFuncSetAttribute(mlp_kernel,  cudaFuncAttributeMaxDynamicSharedMemorySize, MLP_SMEM);
        attr_done = true;
    }

    proj_kernel<<<dim3((VOCAB + 63) / 64, 2), 200, PROJ_SMEM>>>(emb, Wih_f, Wih_b);
    lstm_kernel<<<dim3(BATCH / 8, 2), 832, LSTM_SMEM>>>(X, lengths, Whh_f, b_f,
                                                        Whh_b, b_b, h0, c0);
    mlp_kernel<<<(BATCH * SEQL) / 64, 200, MLP_SMEM>>>(W1, b1, W2, b2);
    viterbi_kernel<<<BATCH / 4, 128>>>(trans, lengths, out, out_size);
}

// round 13
// speedup vs baseline: 1.3452x; 1.1780x over previous
#include <cuda_runtime.h>
#include <cuda_bf16.h>
#include <cstdint>

#define BATCH   512
#define SEQL    512
#define VOCAB   50000
#define EMBD    100
#define HD      100
#define G4      400
#define HIDM    50
#define KT      20
#define NEGF    (-1.0e6f)

typedef unsigned long long ull;

// ------------- device scratch (no cudaMalloc allowed) -------------
__device__ float g_proj[2ull * VOCAB * G4];            // emb @ Wih^T per dir
__device__ float g_enc [(size_t)BATCH * SEQL * 200];   // [hf | hb]
__device__ float g_probs[(size_t)BATCH * SEQL * KT];

// ------------- packed f32x2 helpers -------------
__device__ __forceinline__ ull pack2(float lo, float hi) {
    ull r;
    asm("mov.b64 %0, {%1, %2};" : "=l"(r) : "f"(lo), "f"(hi));
    return r;
}
__device__ __forceinline__ void unpack2(ull v, float& lo, float& hi) {
    asm("mov.b64 {%0, %1}, %2;" : "=f"(lo), "=f"(hi) : "l"(v));
}
__device__ __forceinline__ ull fma2(ull a, ull b, ull c) {
    ull d;
    asm("fma.rn.f32x2 %0, %1, %2, %3;" : "=l"(d) : "l"(a), "l"(b), "l"(c));
    return d;
}
__device__ __forceinline__ float rcpf(float x) {
    float r;
    asm("rcp.approx.f32 %0, %1;" : "=f"(r) : "f"(x));
    return r;
}
__device__ __forceinline__ float sigf(float x) {
    return rcpf(1.0f + __expf(-x));
}
__device__ __forceinline__ float tanhf_(float x) {
    return fmaf(-2.0f, rcpf(__expf(2.0f * x) + 1.0f), 1.0f);
}

// =====================================================================
// K1: proj[dir][v][g] = sum_k emb[v][k] * Wih_dir[g][k]
// =====================================================================
#define PROJ_SMEM ((6600 + 10400) * 4)
__global__ void proj_kernel(const float* __restrict__ emb,
                            const float* __restrict__ Wih_f,
                            const float* __restrict__ Wih_b) {
    extern __shared__ float sm[];
    float* embT = sm;         // [100][66]
    float* wT   = sm + 6600;  // [100][104]

    const int dir = blockIdx.y;
    const float* Wih = dir ? Wih_b : Wih_f;
    float* projD = g_proj + (size_t)dir * VOCAB * G4;

    const int tid = threadIdx.x;
    const int v0  = blockIdx.x * 64;
    const int gx  = tid % 25;
    const int vy  = tid / 25;

    for (int i = tid; i < 64 * EMBD; i += 200) {
        int v = i / EMBD, k = i % EMBD;
        embT[k * 66 + v] = (v0 + v < VOCAB) ? emb[(size_t)(v0 + v) * EMBD + k] : 0.0f;
    }

    for (int ch = 0; ch < 4; ++ch) {
        __syncthreads();
        for (int i = tid; i < 100 * 100; i += 200) {
            int gp = i / 100, k = i % 100;
            wT[k * 104 + gp] = Wih[(size_t)(ch * 100 + gp) * EMBD + k];
        }
        __syncthreads();

        ull acc[4][4];
        #pragma unroll
        for (int p = 0; p < 4; ++p)
            acc[p][0] = acc[p][1] = acc[p][2] = acc[p][3] = 0ull;

        for (int k = 0; k < 100; ++k) {
            float4 wv = *(const float4*)&wT[k * 104 + gx * 4];
            ull w0 = pack2(wv.x, wv.x);
            ull w1 = pack2(wv.y, wv.y);
            ull w2 = pack2(wv.z, wv.z);
            ull w3 = pack2(wv.w, wv.w);
            #pragma unroll
            for (int p = 0; p < 4; ++p) {
                ull e2 = *(const ull*)&embT[k * 66 + vy * 8 + 2 * p];
                acc[p][0] = fma2(e2, w0, acc[p][0]);
                acc[p][1] = fma2(e2, w1, acc[p][1]);
                acc[p][2] = fma2(e2, w2, acc[p][2]);
                acc[p][3] = fma2(e2, w3, acc[p][3]);
            }
        }
        #pragma unroll
        for (int p = 0; p < 4; ++p) {
            float lo[4], hi[4];
            #pragma unroll
            for (int x = 0; x < 4; ++x) unpack2(acc[p][x], lo[x], hi[x]);
            int vA = v0 + vy * 8 + 2 * p, vB = vA + 1;
            if (vA < VOCAB) {
                float4 o = make_float4(lo[0], lo[1], lo[2], lo[3]);
                *(float4*)&projD[(size_t)vA * G4 + ch * 100 + gx * 4] = o;
            }
            if (vB < VOCAB) {
                float4 o = make_float4(hi[0], hi[1], hi[2], hi[3]);
                *(float4*)&projD[(size_t)vB * G4 + ch * 100 + gx * 4] = o;
            }
        }
    }
}

// =====================================================================
// K2: persistent BiLSTM. grid (64, 2); 832 threads; block owns 8 rows.
// Gemm: tid<800, thread = (gate-pair m -> gates 2m,2m+1; k-quarter ks).
//   Per k: 1 LDS.64 (w pair) + 2 LDS.128 (h broadcast) -> 8 FFMA2 (16 MAC).
// Cell: spread over 800 threads, one (row r, hidden j) each; 4-way partial
//   sums read from padded smem; x-projection gathers issued in phase 1 so
//   the k-loop covers their global latency. tid 800..807: token prefetch.
// =====================================================================
#define LSTM_SMEM 227328
__global__ __launch_bounds__(832, 1)
void lstm_kernel(const int* __restrict__ X, const int* __restrict__ lengths,
                 const float* __restrict__ Whh_f, const float* __restrict__ b_f,
                 const float* __restrict__ Whh_b, const float* __restrict__ b_b,
                 const float* __restrict__ h0, const float* __restrict__ c0) {
    extern __shared__ char smraw[];
    float* whhT = (float*)smraw;               // [100][400]          160000 B
    float* h_f  = (float*)(smraw + 160000);    // [100][8]            3200 B
    ull*   gshU = (ull*)  (smraw + 163200);    // [4][400][5] padded  64000 B
    float* gshF = (float*)(smraw + 163200);    // float view
    int*   tokS = (int*)  (smraw + 227200);    // [2][8]
    int*   lenS = tokS + 16;                   // [8]

    const int dir = blockIdx.y;
    const int b0  = blockIdx.x * 8;
    const int tid = threadIdx.x;
    const float* Whh = dir ? Whh_b : Whh_f;
    const float* bia = dir ? b_b : b_f;
    const float* proj = g_proj + (size_t)dir * VOCAB * G4;

    for (int i = tid; i < G4 * HD; i += 832) {
        int g = i / HD, k = i % HD;
        whhT[k * G4 + g] = Whh[i];
    }
    if (tid < 8) lenS[tid] = lengths[b0 + tid];

    const bool gm = tid < 800;
    const int r  = gm ? tid / 100 : 0;   // cell row 0..7
    const int j  = gm ? tid % 100 : 0;   // cell hidden
    const int m  = gm ? tid % 200 : 0;   // gemm gate pair -> gates 2m, 2m+1
    const int ks = gm ? tid / 200 : 0;   // gemm k-quarter
    const int k0 = ks * 25;

    float bj0 = 0, bj1 = 0, bj2 = 0, bj3 = 0, cst = 0;
    if (gm) {
        bj0 = bia[j];
        bj1 = bia[j + 100];
        bj2 = bia[j + 200];
        bj3 = bia[j + 300];
        cst = c0[((size_t)dir * BATCH + b0 + r) * HD + j];
        h_f[j * 8 + r] = h0[((size_t)dir * BATCH + b0 + r) * HD + j];
    }
    if (tid < 8) {
        int len = lenS[tid];   // lenS written by this same thread above
        int it = dir ? (len - 1) : 0;
        tokS[tid] = X[(size_t)(b0 + tid) * SEQL + it];
    }
    __syncthreads();

    int lenmax = lenS[0];
    #pragma unroll
    for (int rr = 1; rr < 8; ++rr) lenmax = max(lenmax, lenS[rr]);

    for (int t = 0; t < lenmax; ++t) {
        const int buf = t & 1;
        float xv0 = 0, xv1 = 0, xv2 = 0, xv3 = 0;

        // ---------- phase 1: gemm (+ cell's x-gathers under the k-loop) ----------
        if (gm) {
            const int tok = tokS[buf * 8 + r];
            const float* pp = proj + (size_t)tok * G4 + j;
            xv0 = __ldg(pp);
            xv1 = __ldg(pp + 100);
            xv2 = __ldg(pp + 200);
            xv3 = __ldg(pp + 300);

            ull a00 = 0, a01 = 0, a02 = 0, a03 = 0;
            ull a10 = 0, a11 = 0, a12 = 0, a13 = 0;
            const float* wp = whhT + 2 * m;
            #pragma unroll 5
            for (int k = k0; k < k0 + 25; ++k) {
                float2 w = *(const float2*)&wp[k * G4];
                ull wA = pack2(w.x, w.x);
                ull wB = pack2(w.y, w.y);
                ulonglong2 hA = *(const ulonglong2*)&h_f[k * 8];       // rows 0-3
                ulonglong2 hB = *(const ulonglong2*)&h_f[k * 8 + 4];   // rows 4-7
                a00 = fma2(hA.x, wA, a00);
                a01 = fma2(hA.y, wA, a01);
                a02 = fma2(hB.x, wA, a02);
                a03 = fma2(hB.y, wA, a03);
                a10 = fma2(hA.x, wB, a10);
                a11 = fma2(hA.y, wB, a11);
                a12 = fma2(hB.x, wB, a12);
                a13 = fma2(hB.y, wB, a13);
            }
            ull* sA = gshU + (size_t)ks * 2000 + (2 * m) * 5;
            sA[0] = a00; sA[1] = a01; sA[2] = a02; sA[3] = a03;
            sA[5] = a10; sA[6] = a11; sA[7] = a12; sA[8] = a13;
        } else if (tid >= 800 && tid < 808) {
            int rr = tid - 800, len = lenS[rr];
            int tn = t + 1; if (tn >= SEQL) tn = SEQL - 1;
            int it = dir ? ((tn < len) ? (len - 1 - tn) : tn) : tn;
            tokS[(buf ^ 1) * 8 + rr] = X[(size_t)(b0 + rr) * SEQL + it];
        }
        __syncthreads();

        // ---------- phase 2: cell (one (r, j) per thread) ----------
        if (gm) {
            const int base = j * 10 + r;    // float idx within a ks-slab
            float gi_ = xv0 + bj0;
            float gf_ = xv1 + bj1;
            float gg_ = xv2 + bj2;
            float go_ = xv3 + bj3;
            #pragma unroll
            for (int s = 0; s < 4; ++s) {
                const float* gp = gshF + s * 4000 + base;
                gi_ += gp[0];
                gf_ += gp[1000];
                gg_ += gp[2000];
                go_ += gp[3000];
            }
            cst = sigf(gf_) * cst + sigf(gi_) * tanhf_(gg_);
            float h = sigf(go_) * tanhf_(cst);
            h_f[j * 8 + r] = h;

            int len = lenS[r];
            int ot = dir ? ((t < len) ? (len - 1 - t) : t) : t;
            g_enc[((size_t)(b0 + r) * SEQL + ot) * 200 + dir * HD + j] = h;
        }
        __syncthreads();
    }
}

// =====================================================================
// K3: MLP, 64 tokens/block, 200 threads, f32x2-packed over token pairs.
// =====================================================================
#define MLP_SMEM (27984 * 4)
__global__ void mlp_kernel(const float* __restrict__ W1, const float* __restrict__ b1,
                           const float* __restrict__ W2, const float* __restrict__ b2) {
    extern __shared__ float sm[];
    float* encT = sm;            // [200][66]
    float* w1T  = sm + 13200;    // [200][52]
    float* hidT = sm + 23600;    // [50][66]
    float* w2T  = sm + 26900;    // [50][20]
    float* b1S  = sm + 27900;    // [50]
    float* b2S  = sm + 27952;    // [20]

    const int tid = threadIdx.x;
    const size_t tok0 = (size_t)blockIdx.x * 64;

    for (int i = tid; i < 64 * 200; i += 200) {
        int t = i / 200, k = i % 200;
        encT[k * 66 + t] = g_enc[(tok0 + t) * 200 + k];
    }
    for (int i = tid; i < HIDM * 200; i += 200) {
        int m = i / 200, k = i % 200;
        w1T[k * 52 + m] = W1[i];
    }
    for (int i = tid; i < KT * HIDM; i += 200) {
        int jj = i / HIDM, m = i % HIDM;
        w2T[m * KT + jj] = W2[i];
    }
    if (tid < HIDM) b1S[tid] = b1[tid];
    if (tid < KT)   b2S[tid] = b2[tid];
    __syncthreads();

    const int mg = tid % 25, tg = tid / 25;
    {
        ull acc0[4] = {0, 0, 0, 0};
        ull acc1[4] = {0, 0, 0, 0};
        for (int k = 0; k < 200; ++k) {
            float2 wp = *(const float2*)&w1T[k * 52 + 2 * mg];
            ull wA = pack2(wp.x, wp.x);
            ull wB = pack2(wp.y, wp.y);
            #pragma unroll
            for (int p = 0; p < 4; ++p) {
                ull e2 = *(const ull*)&encT[k * 66 + tg * 8 + 2 * p];
                acc0[p] = fma2(e2, wA, acc0[p]);
                acc1[p] = fma2(e2, wB, acc1[p]);
            }
        }
        float bb0 = b1S[2 * mg], bb1 = b1S[2 * mg + 1];
        #pragma unroll
        for (int p = 0; p < 4; ++p) {
            float x0, x1, y0, y1;
            unpack2(acc0[p], x0, x1);
            unpack2(acc1[p], y0, y1);
            int tk = tg * 8 + 2 * p;
            hidT[(2 * mg) * 66 + tk]         = fmaxf(x0 + bb0, 0.f);
            hidT[(2 * mg) * 66 + tk + 1]     = fmaxf(x1 + bb0, 0.f);
            hidT[(2 * mg + 1) * 66 + tk]     = fmaxf(y0 + bb1, 0.f);
            hidT[(2 * mg + 1) * 66 + tk + 1] = fmaxf(y1 + bb1, 0.f);
        }
    }
    __syncthreads();

    for (int it = tid; it < 32 * KT; it += 200) {
        int tp = it / KT, jj = it % KT;
        float bb = b2S[jj];
        ull acc = pack2(bb, bb);
        #pragma unroll 10
        for (int m = 0; m < HIDM; ++m) {
            ull h2 = *(const ull*)&hidT[m * 66 + 2 * tp];
            float w = w2T[m * KT + jj];
            acc = fma2(h2, pack2(w, w), acc);
        }
        float o0, o1;
        unpack2(acc, o0, o1);
        g_probs[(tok0 + 2 * tp) * KT + jj]     = o0;
        g_probs[(tok0 + 2 * tp + 1) * KT + jj] = o1;
    }
}

// =====================================================================
// K4: Viterbi. 16 warps/block (16 batch rows), grid 32 -> 4 warps/SMSP
// for latency interleaving. trans column in registers; fmax-tree + mask.
// =====================================================================
#define VIT_WARPS 16
#define VIT_SMEM  (VIT_WARPS * SEQL * KT)
__global__ __launch_bounds__(VIT_WARPS * 32, 1)
void viterbi_kernel(const float* __restrict__ trans,
                    const int* __restrict__ lengths,
                    float* __restrict__ out, int out_size) {
    extern __shared__ unsigned char bpRaw[];   // [16][512][20]

    const int tid = threadIdx.x;
    const int w = tid / 32, lane = tid % 32;
    const int b = blockIdx.x * VIT_WARPS + w;
    unsigned char* bp = bpRaw + (size_t)w * SEQL * KT;

    const int len = lengths[b];
    const int ln = (lane < KT) ? lane : 0;

    float trn[KT];
    #pragma unroll
    for (int i = 0; i < KT; ++i) trn[i] = trans[i * KT + ln];
    const float tend = trans[ln * KT + (KT - 1)];   // trans[:, END]

    float alpha = (lane == (KT - 2)) ? 0.0f : NEGF; // START = K-2
    const float* pb = g_probs + (size_t)b * SEQL * KT;

    float p_cur = pb[ln];
    for (int t = 0; t < len; ++t) {
        int tn = (t + 1 < len) ? (t + 1) : t;
        float p_nxt = pb[(size_t)tn * KT + ln];

        float v[KT];
        #pragma unroll
        for (int i = 0; i < KT; ++i) {
            float ai = __shfl_sync(0xffffffffu, alpha, i);
            v[i] = ai + trn[i];
        }
        float m[10];
        #pragma unroll
        for (int i = 0; i < 10; ++i) m[i] = fmaxf(v[i], v[i + 10]);
        #pragma unroll
        for (int i = 0; i < 5; ++i) m[i] = fmaxf(m[i], m[i + 5]);
        float best = fmaxf(fmaxf(fmaxf(m[0], m[1]), fmaxf(m[2], m[3])), m[4]);

        unsigned msk = 0;
        #pragma unroll
        for (int i = 0; i < KT; ++i)
            if (v[i] == best) msk |= (1u << i);
        int bi = __ffs(msk) - 1;

        alpha = best + p_cur;
        if (lane < KT) bp[t * KT + lane] = (unsigned char)bi;
        p_cur = p_nxt;
    }

    float fin = alpha + tend;
    float v[KT];
    #pragma unroll
    for (int i = 0; i < KT; ++i) v[i] = __shfl_sync(0xffffffffu, fin, i);
    float m[10];
    #pragma unroll
    for (int i = 0; i < 10; ++i) m[i] = fmaxf(v[i], v[i + 10]);
    #pragma unroll
    for (int i = 0; i < 5; ++i) m[i] = fmaxf(m[i], m[i + 5]);
    float best = fmaxf(fmaxf(fmaxf(m[0], m[1]), fmaxf(m[2], m[3])), m[4]);
    unsigned msk = 0;
    #pragma unroll
    for (int i = 0; i < KT; ++i)
        if (v[i] == best) msk |= (1u << i);
    int bj = __ffs(msk) - 1;

    if (lane == 0) {
        out[b] = best;
        if (out_size >= BATCH + BATCH * SEQL) {
            float* pout = out + BATCH + (size_t)b * SEQL;
            int cur = bj;
            for (int t = SEQL - 1; t >= 0; --t) {
                if (t >= len) {
                    pout[t] = -1.0f;
                } else {
                    pout[t] = (float)cur;
                    cur = bp[t * KT + cur];
                }
            }
        }
    }
}

// =====================================================================
extern "C" void kernel_launch(void* const* d_in, const int* in_sizes, int n_in,
                              void* d_out, int out_size) {
    const int*   X       = (const int*)d_in[0];
    const int*   lengths = (const int*)d_in[1];
    const float* emb     = (const float*)d_in[2];
    const float* Wih_f   = (const float*)d_in[3];
    const float* Whh_f   = (const float*)d_in[4];
    const float* b_f     = (const float*)d_in[5];
    const float* Wih_b   = (const float*)d_in[6];
    const float* Whh_b   = (const float*)d_in[7];
    const float* b_b     = (const float*)d_in[8];
    const float* h0      = (const float*)d_in[9];
    const float* c0      = (const float*)d_in[10];
    const float* W1      = (const float*)d_in[11];
    const float* b1      = (const float*)d_in[12];
    const float* W2      = (const float*)d_in[13];
    const float* b2      = (const float*)d_in[14];
    const float* trans   = (const float*)d_in[15];
    float* out = (float*)d_out;

    cudaFuncSetAttribute(proj_kernel,    cudaFuncAttributeMaxDynamicSharedMemorySize, PROJ_SMEM);
    cudaFuncSetAttribute(lstm_kernel,    cudaFuncAttributeMaxDynamicSharedMemorySize, LSTM_SMEM);
    cudaFuncSetAttribute(mlp_kernel,     cudaFuncAttributeMaxDynamicSharedMemorySize, MLP_SMEM);
    cudaFuncSetAttribute(viterbi_kernel, cudaFuncAttributeMaxDynamicSharedMemorySize, VIT_SMEM);

    proj_kernel<<<dim3((VOCAB + 63) / 64, 2), 200, PROJ_SMEM>>>(emb, Wih_f, Wih_b);
    lstm_kernel<<<dim3(BATCH / 8, 2), 832, LSTM_SMEM>>>(X, lengths, Whh_f, b_f,
                                                        Whh_b, b_b, h0, c0);
    mlp_kernel<<<(BATCH * SEQL) / 64, 200, MLP_SMEM>>>(W1, b1, W2, b2);
    viterbi_kernel<<<BATCH / VIT_WARPS, VIT_WARPS * 32, VIT_SMEM>>>(trans, lengths,
                                                                    out, out_size);
}